// round 1
// baseline (speedup 1.0000x reference)
#include <cuda_runtime.h>
#include <math.h>

#define BB  64
#define NN  100
#define MM  99
#define NIN 32
#define NG  32
#define NF  64

// scratch for x = features @ W0  (1.6 MB)
__device__ float g_x[BB * NN * NF];

// ---------------------------------------------------------------------------
// Kernel 1: x = features @ W0   [B*N, NIN] @ [NIN, NF] -> [B*N, NF]
// ---------------------------------------------------------------------------
__global__ void x_kernel(const float* __restrict__ features,
                         const float* __restrict__ W0)
{
    int idx = blockIdx.x * blockDim.x + threadIdx.x;
    if (idx >= BB * NN * NF) return;
    int f   = idx & (NF - 1);
    int row = idx >> 6;
    const float* feat = features + row * NIN;
    float acc = 0.f;
#pragma unroll
    for (int k = 0; k < NIN; k++)
        acc = fmaf(feat[k], W0[k * NF + f], acc);
    g_x[idx] = acc;
}

// ---------------------------------------------------------------------------
// Kernel 2: fused cfconv + attention + output MLP.
// One block per (b, n) atom. 128 threads = 2 halves x 64 feature lanes.
// Half h processes neighbors m = 2*it + h. Thread j owns columns W1[:,j],
// W2[:,j] in registers; rbf and hidden vectors are exchanged via shared
// (broadcast LDS.128). Online softmax per half, merged at the end.
// ---------------------------------------------------------------------------
__global__ __launch_bounds__(128, 4)
void interaction_kernel(const float* __restrict__ rbf,
                        const int*   __restrict__ nbr_list,
                        const float* __restrict__ W1, const float* __restrict__ b1,
                        const float* __restrict__ W2, const float* __restrict__ b2,
                        const float* __restrict__ nbrf,
                        const float* __restrict__ W3, const float* __restrict__ b3,
                        const float* __restrict__ W4, const float* __restrict__ b4,
                        float* __restrict__ out,
                        float* __restrict__ attn)
{
    __shared__ float s_x[NN * NF];          // x for this frame, 25.6 KB
    __shared__ float s_rbf[2][NG];
    __shared__ float s_h[2][NF];
    __shared__ float s_logits[MM + 1];
    __shared__ float s_red[4];
    __shared__ float s_mrg[NF + 2];         // half-1 agg + its (max, denom)
    __shared__ float s_vec[NF];             // final agg broadcast
    __shared__ float s_fin[2];              // final (max, denom)

    const int tid = threadIdx.x;
    const int h   = tid >> 6;               // half: 0 or 1
    const int j   = tid & 63;               // feature lane
    const int bn  = blockIdx.x;
    const int b   = bn / NN;

    // Register-resident weight columns for this feature lane.
    float w1c[NG];
#pragma unroll
    for (int k = 0; k < NG; k++) w1c[k] = W1[k * NF + j];
    float w2c[NF];
#pragma unroll
    for (int k = 0; k < NF; k++) w2c[k] = W2[k * NF + j];
    const float b1j = b1[j];
    const float b2j = b2[j];
    const float nfj = nbrf[j];

    // Stage x[b] into shared.
    {
        const float* xg = g_x + b * (NN * NF);
        for (int i = tid; i < NN * NF; i += 128) s_x[i] = xg[i];
    }
    __syncthreads();

    const float* rbf_bn = rbf + (size_t)bn * MM * NG;
    const int*   nl_bn  = nbr_list + bn * MM;

    float m_run = -1e30f;   // running max (identical across the 64 lanes of a half)
    float d_run = 0.f;      // running denom
    float agg   = 0.f;      // running weighted sum for feature j

    for (int it = 0; it < (MM + 1) / 2; it++) {
        const int  m     = 2 * it + h;
        const bool valid = (m < MM);

        if (j < NG)
            s_rbf[h][j] = valid ? rbf_bn[m * NG + j] : 0.f;
        __syncthreads();                                    // A

        // GEMM1 + tanh: hidden[j] = tanh(b1 + rbf . W1[:,j])
        float acc = b1j;
        {
            const float4* r4 = (const float4*)s_rbf[h];
#pragma unroll
            for (int k4 = 0; k4 < NG / 4; k4++) {
                float4 r = r4[k4];
                acc = fmaf(r.x, w1c[4 * k4 + 0], acc);
                acc = fmaf(r.y, w1c[4 * k4 + 1], acc);
                acc = fmaf(r.z, w1c[4 * k4 + 2], acc);
                acc = fmaf(r.w, w1c[4 * k4 + 3], acc);
            }
        }
        s_h[h][j] = tanhf(acc);
        __syncthreads();                                    // B

        // GEMM2: f[j] = b2 + hidden . W2[:,j]
        float fv = b2j;
        {
            const float4* h4 = (const float4*)s_h[h];
#pragma unroll
            for (int k4 = 0; k4 < NF / 4; k4++) {
                float4 hh = h4[k4];
                fv = fmaf(hh.x, w2c[4 * k4 + 0], fv);
                fv = fmaf(hh.y, w2c[4 * k4 + 1], fv);
                fv = fmaf(hh.z, w2c[4 * k4 + 2], fv);
                fv = fmaf(hh.w, w2c[4 * k4 + 3], fv);
            }
        }

        const int  nbr = valid ? nl_bn[m] : 0;
        const float cf = s_x[nbr * NF + j] * fv;            // conv_features[j]

        // logit = sum_j cf[j] * nbrf[j]  (reduce over the 64 lanes of a half)
        float p = cf * nfj;
#pragma unroll
        for (int off = 16; off > 0; off >>= 1)
            p += __shfl_xor_sync(0xffffffffu, p, off);
        if ((tid & 31) == 0) s_red[tid >> 5] = p;
        __syncthreads();                                    // C
        const float l = s_red[2 * h] + s_red[2 * h + 1];

        if (valid) {
            if (j == 0) s_logits[m] = l;
            const float mn    = fmaxf(m_run, l);
            const float scale = __expf(m_run - mn);
            const float e     = __expf(l - mn);
            agg   = agg * scale + e * cf;
            d_run = d_run * scale + e;
            m_run = mn;
        }
        __syncthreads();                                    // D (protect reuse)
    }

    // Merge the two halves' online-softmax state.
    if (h == 1) {
        s_mrg[j] = agg;
        if (j == 0) { s_mrg[NF] = m_run; s_mrg[NF + 1] = d_run; }
    }
    __syncthreads();
    if (h == 0) {
        const float m1 = s_mrg[NF], d1 = s_mrg[NF + 1];
        const float mn = fmaxf(m_run, m1);
        const float e0 = __expf(m_run - mn);
        const float e1 = __expf(m1 - mn);
        const float D  = d_run * e0 + d1 * e1;
        float a = (agg * e0 + s_mrg[j] * e1) / D;
        s_vec[j] = a;
        if (j == 0) { s_fin[0] = mn; s_fin[1] = D; }
    }
    __syncthreads();

    // attn outputs
    {
        const float Mf = s_fin[0];
        const float Df = s_fin[1];
        float* attn_bn = attn + bn * MM;
        if (tid < MM)
            attn_bn[tid] = __expf(s_logits[tid] - Mf) / Df;
    }

    // Output MLP: out = tanh(agg @ W3 + b3) @ W4 + b4  (redundant across halves)
    float t = b3[j];
#pragma unroll
    for (int k = 0; k < NF; k++)
        t = fmaf(s_vec[k], W3[k * NF + j], t);
    t = tanhf(t);
    __syncthreads();
    if (h == 0) s_h[0][j] = t;
    __syncthreads();
    float o = b4[j];
#pragma unroll
    for (int k = 0; k < NF; k++)
        o = fmaf(s_h[0][k], W4[k * NF + j], o);
    if (h == 0) out[bn * NF + j] = o;
}

// ---------------------------------------------------------------------------
extern "C" void kernel_launch(void* const* d_in, const int* in_sizes, int n_in,
                              void* d_out, int out_size)
{
    const float* features = (const float*)d_in[0];
    const float* rbf      = (const float*)d_in[1];
    const int*   nbr      = (const int*)  d_in[2];
    const float* W0       = (const float*)d_in[3];
    const float* W1       = (const float*)d_in[4];
    const float* b1       = (const float*)d_in[5];
    const float* W2       = (const float*)d_in[6];
    const float* b2       = (const float*)d_in[7];
    const float* nbrf     = (const float*)d_in[8];
    const float* W3       = (const float*)d_in[9];
    const float* b3       = (const float*)d_in[10];
    const float* W4       = (const float*)d_in[11];
    const float* b4       = (const float*)d_in[12];

    float* out  = (float*)d_out;                 // [B, N, NF]
    float* attn = out + BB * NN * NF;            // [B, N, M]

    x_kernel<<<(BB * NN * NF + 255) / 256, 256>>>(features, W0);
    interaction_kernel<<<BB * NN, 128>>>(rbf, nbr, W1, b1, W2, b2, nbrf,
                                         W3, b3, W4, b4, out, attn);
}

// round 2
// speedup vs baseline: 1.2106x; 1.2106x over previous
#include <cuda_runtime.h>
#include <math.h>

#define BB  64
#define NN  100
#define MM  99
#define NIN 32
#define NG  32
#define NF  64
#define CH  16                      // neighbors per chunk
#define NCHUNK ((MM + CH - 1) / CH) // 7

// scratch for x = features @ W0  (1.6 MB)
__device__ float g_x[BB * NN * NF];

__device__ __forceinline__ float tanh_fast(float x) {
    float y;
    asm("tanh.approx.f32 %0, %1;" : "=f"(y) : "f"(x));
    return y;
}

// ---------------------------------------------------------------------------
// Kernel 1: x = features @ W0   [B*N, NIN] @ [NIN, NF] -> [B*N, NF]
// ---------------------------------------------------------------------------
__global__ void x_kernel(const float* __restrict__ features,
                         const float* __restrict__ W0)
{
    int idx = blockIdx.x * blockDim.x + threadIdx.x;
    if (idx >= BB * NN * NF) return;
    int f   = idx & (NF - 1);
    int row = idx >> 6;
    const float* feat = features + row * NIN;
    float acc = 0.f;
#pragma unroll
    for (int k = 0; k < NIN; k++)
        acc = fmaf(feat[k], W0[k * NF + f], acc);
    g_x[idx] = acc;
}

// ---------------------------------------------------------------------------
// Kernel 2: fused cfconv + attention + output MLP, chunked.
// One block per (b,n) atom, 128 threads = 2 halves x 64 feature lanes.
// Per chunk of 16 neighbors: half h owns neighbors [8h, 8h+8). Thread j owns
// W1[:,j], W2[:,j] in registers. 3 barriers per chunk.
// ---------------------------------------------------------------------------
__global__ __launch_bounds__(128)
void interaction_kernel(const float* __restrict__ rbf,
                        const int*   __restrict__ nbr_list,
                        const float* __restrict__ W1, const float* __restrict__ b1,
                        const float* __restrict__ W2, const float* __restrict__ b2,
                        const float* __restrict__ nbrf,
                        const float* __restrict__ W3, const float* __restrict__ b3,
                        const float* __restrict__ W4, const float* __restrict__ b4,
                        float* __restrict__ out,
                        float* __restrict__ attn)
{
    __shared__ float s_x[NN * NF];        // 25.6 KB
    __shared__ float s_rbf[CH][NG];       // 2 KB
    __shared__ float s_h[CH][NF];         // 4 KB
    __shared__ int   s_nl[CH];
    __shared__ float s_wpart[4][CH];      // per-warp logit partials
    __shared__ float s_logits[NCHUNK * CH];
    __shared__ float s_mrg[NF + 2];
    __shared__ float s_vec[NF];
    __shared__ float s_fin[2];
    __shared__ float s_hid[NF];

    const int tid = threadIdx.x;
    const int h   = tid >> 6;             // half: 0 or 1
    const int j   = tid & 63;             // feature lane
    const int wid = tid >> 5;             // warp 0..3
    const int bn  = blockIdx.x;
    const int b   = bn / NN;

    // Register-resident weight columns for this feature lane.
    float w1c[NG];
#pragma unroll
    for (int k = 0; k < NG; k++) w1c[k] = W1[k * NF + j];
    float w2c[NF];
#pragma unroll
    for (int k = 0; k < NF; k++) w2c[k] = W2[k * NF + j];
    const float b1j = b1[j];
    const float b2j = b2[j];
    const float nfj = nbrf[j];

    // Stage x[b] into shared (float4).
    {
        const float4* xg = (const float4*)(g_x + b * (NN * NF));
        float4* xs = (float4*)s_x;
        for (int i = tid; i < NN * NF / 4; i += 128) xs[i] = xg[i];
    }

    const float* rbf_bn = rbf + (size_t)bn * MM * NG;
    const int*   nl_bn  = nbr_list + bn * MM;

    float m_run = -1e30f;   // running max (identical across the 64 lanes of a half)
    float d_run = 0.f;      // running denom
    float agg   = 0.f;      // running weighted sum for feature j

    for (int ch = 0; ch < NCHUNK; ch++) {
        // ---- stage chunk rbf + neighbor list (1 barrier protects reuse too)
        __syncthreads();
        {
            // 128 threads x 1 float4 = 16 rows x 32 cols
            int ml = tid >> 3;            // 0..15
            int k4 = tid & 7;             // float4 index within row
            int m  = ch * CH + ml;
            float4 v = make_float4(0.f, 0.f, 0.f, 0.f);
            if (m < MM)
                v = *(const float4*)(rbf_bn + m * NG + 4 * k4);
            *(float4*)&s_rbf[ml][4 * k4] = v;
            if (tid < CH) {
                int mm = ch * CH + tid;
                s_nl[tid] = (mm < MM) ? nl_bn[mm] : 0;
            }
        }
        __syncthreads();

        // ---- GEMM1 + tanh for this half's 8 neighbors
        {
            float acc[8];
#pragma unroll
            for (int i = 0; i < 8; i++) acc[i] = b1j;
#pragma unroll
            for (int k4 = 0; k4 < NG / 4; k4++) {
#pragma unroll
                for (int i = 0; i < 8; i++) {
                    float4 r = *(const float4*)&s_rbf[8 * h + i][4 * k4];
                    acc[i] = fmaf(r.x, w1c[4 * k4 + 0], acc[i]);
                    acc[i] = fmaf(r.y, w1c[4 * k4 + 1], acc[i]);
                    acc[i] = fmaf(r.z, w1c[4 * k4 + 2], acc[i]);
                    acc[i] = fmaf(r.w, w1c[4 * k4 + 3], acc[i]);
                }
            }
#pragma unroll
            for (int i = 0; i < 8; i++)
                s_h[8 * h + i][j] = tanh_fast(acc[i]);
        }
        __syncthreads();

        // ---- GEMM2 + gather + per-warp logit partials
        float cf[8];
        {
            float fv[8];
#pragma unroll
            for (int i = 0; i < 8; i++) fv[i] = b2j;
#pragma unroll
            for (int k4 = 0; k4 < NF / 4; k4++) {
#pragma unroll
                for (int i = 0; i < 8; i++) {
                    float4 hh = *(const float4*)&s_h[8 * h + i][4 * k4];
                    fv[i] = fmaf(hh.x, w2c[4 * k4 + 0], fv[i]);
                    fv[i] = fmaf(hh.y, w2c[4 * k4 + 1], fv[i]);
                    fv[i] = fmaf(hh.z, w2c[4 * k4 + 2], fv[i]);
                    fv[i] = fmaf(hh.w, w2c[4 * k4 + 3], fv[i]);
                }
            }
#pragma unroll
            for (int i = 0; i < 8; i++) {
                int nbr = s_nl[8 * h + i];
                cf[i] = s_x[nbr * NF + j] * fv[i];
                float p = cf[i] * nfj;
#pragma unroll
                for (int off = 16; off > 0; off >>= 1)
                    p += __shfl_xor_sync(0xffffffffu, p, off);
                if ((tid & 31) == 0) s_wpart[wid][8 * h + i] = p;
            }
        }
        __syncthreads();

        // ---- combine partials -> logits, online softmax update (no barrier)
#pragma unroll
        for (int i = 0; i < 8; i++) {
            int ml = 8 * h + i;
            int m  = ch * CH + ml;
            float l = s_wpart[2 * h][ml] + s_wpart[2 * h + 1][ml];
            if (m < MM) {
                if (j == 0) s_logits[m] = l;
                float mn    = fmaxf(m_run, l);
                float scale = __expf(m_run - mn);
                float e     = __expf(l - mn);
                agg   = agg * scale + e * cf[i];
                d_run = d_run * scale + e;
                m_run = mn;
            }
        }
    }

    // ---- merge the two halves' online-softmax state
    __syncthreads();
    if (h == 1) {
        s_mrg[j] = agg;
        if (j == 0) { s_mrg[NF] = m_run; s_mrg[NF + 1] = d_run; }
    }
    __syncthreads();
    if (h == 0) {
        const float m1 = s_mrg[NF], d1 = s_mrg[NF + 1];
        const float mn = fmaxf(m_run, m1);
        const float e0 = __expf(m_run - mn);
        const float e1 = __expf(m1 - mn);
        const float D  = d_run * e0 + d1 * e1;
        s_vec[j] = (agg * e0 + s_mrg[j] * e1) / D;
        if (j == 0) { s_fin[0] = mn; s_fin[1] = D; }
    }
    __syncthreads();

    // ---- attn outputs
    {
        const float Mf = s_fin[0];
        const float Df = s_fin[1];
        if (tid < MM)
            attn[bn * MM + tid] = __expf(s_logits[tid] - Mf) / Df;
    }

    // ---- output MLP: out = tanh(agg @ W3 + b3) @ W4 + b4
    float t = b3[j];
#pragma unroll
    for (int k = 0; k < NF; k++)
        t = fmaf(s_vec[k], W3[k * NF + j], t);
    t = tanh_fast(t);
    if (h == 0) s_hid[j] = t;
    __syncthreads();
    if (h == 0) {
        float o = b4[j];
#pragma unroll
        for (int k = 0; k < NF; k++)
            o = fmaf(s_hid[k], W4[k * NF + j], o);
        out[bn * NF + j] = o;
    }
}

// ---------------------------------------------------------------------------
extern "C" void kernel_launch(void* const* d_in, const int* in_sizes, int n_in,
                              void* d_out, int out_size)
{
    const float* features = (const float*)d_in[0];
    const float* rbf      = (const float*)d_in[1];
    const int*   nbr      = (const int*)  d_in[2];
    const float* W0       = (const float*)d_in[3];
    const float* W1       = (const float*)d_in[4];
    const float* b1       = (const float*)d_in[5];
    const float* W2       = (const float*)d_in[6];
    const float* b2       = (const float*)d_in[7];
    const float* nbrf     = (const float*)d_in[8];
    const float* W3       = (const float*)d_in[9];
    const float* b3       = (const float*)d_in[10];
    const float* W4       = (const float*)d_in[11];
    const float* b4       = (const float*)d_in[12];

    float* out  = (float*)d_out;                 // [B, N, NF]
    float* attn = out + BB * NN * NF;            // [B, N, M]

    x_kernel<<<(BB * NN * NF + 255) / 256, 256>>>(features, W0);
    interaction_kernel<<<BB * NN, 128>>>(rbf, nbr, W1, b1, W2, b2, nbrf,
                                         W3, b3, W4, b4, out, attn);
}

// round 4
// speedup vs baseline: 1.9075x; 1.5756x over previous
#include <cuda_runtime.h>
#include <math.h>
#include <cstdint>

#define BB  64
#define NN  100
#define MM  99
#define NIN 32
#define NG  32
#define NF  64

// ---------------- smem layout (bytes) --------------------------------------
// U region: A1 (rbf, [128][68] f32, cols 0..31 used) then reused in-place as
//           H  (tanh output, [128][68], cols 0..63)
#define U_OFF    0
#define U_STRIDE 68                      // floats
#define B1_OFF   34816                   // W1^T [64][36] f32
#define B1_STR   36
#define B2_OFF   44032                   // W2^T [64][68] f32
#define B2_STR   68
#define X_OFF    61440                   // x rows [100][66] f32
#define X_STR    66
#define NL_OFF   87840                   // nbr list [100] int
#define BV_OFF   88240                   // b1 [64]
#define LG_OFF   88496                   // logits [100]
#define MG_OFF   88896                   // merge states [4][4][18]
#define VEC_OFF  90048                   // final agg [64]
#define FIN_OFF  90304                   // (max, denom)
#define HID_OFF  90312                   // hidden [64]
#define SMEM_TOTAL 90624

static __device__ __forceinline__ float tanh_fast(float x) {
    float y; asm("tanh.approx.f32 %0, %1;" : "=f"(y) : "f"(x)); return y;
}
static __device__ __forceinline__ float to_tf32(float x) {
    uint32_t u; asm("cvt.rna.tf32.f32 %0, %1;" : "=r"(u) : "f"(x));
    return __uint_as_float(u);
}

#define MMA_TF32(c, a, b0, b1v)                                                    \
    asm volatile("mma.sync.aligned.m16n8k8.row.col.f32.tf32.tf32.f32 "             \
        "{%0,%1,%2,%3},{%4,%5,%6,%7},{%8,%9},{%0,%1,%2,%3};"                       \
        : "+f"((c)[0]), "+f"((c)[1]), "+f"((c)[2]), "+f"((c)[3])                   \
        : "r"((a)[0]), "r"((a)[1]), "r"((a)[2]), "r"((a)[3]), "r"(b0), "r"(b1v))

// scratch for x = features @ W0
__device__ float g_x[BB * NN * NF];

// ---------------------------------------------------------------------------
__global__ void x_kernel(const float* __restrict__ features,
                         const float* __restrict__ W0)
{
    int idx = blockIdx.x * blockDim.x + threadIdx.x;
    if (idx >= BB * NN * NF) return;
    int f   = idx & (NF - 1);
    int row = idx >> 6;
    const float* feat = features + row * NIN;
    float acc = 0.f;
#pragma unroll
    for (int k = 0; k < NIN; k++)
        acc = fmaf(feat[k], W0[k * NF + f], acc);
    g_x[idx] = acc;
}

// ---------------------------------------------------------------------------
// One CTA per atom: mma.sync tf32 filter GEMMs + fused epilogue.
// ---------------------------------------------------------------------------
__global__ __launch_bounds__(128)
void interaction_kernel(const float* __restrict__ rbf,
                        const int*   __restrict__ nbr_list,
                        const float* __restrict__ W1, const float* __restrict__ b1,
                        const float* __restrict__ W2, const float* __restrict__ b2,
                        const float* __restrict__ nbrf,
                        const float* __restrict__ W3, const float* __restrict__ b3,
                        const float* __restrict__ W4, const float* __restrict__ b4,
                        float* __restrict__ out,
                        float* __restrict__ attn)
{
    extern __shared__ __align__(16) char smem[];
    float* sU  = (float*)(smem + U_OFF);     // A1 then H
    float* sB1 = (float*)(smem + B1_OFF);
    float* sB2 = (float*)(smem + B2_OFF);
    float* sX  = (float*)(smem + X_OFF);
    int*   sNL = (int*)  (smem + NL_OFF);
    float* sBV = (float*)(smem + BV_OFF);
    float* sLG = (float*)(smem + LG_OFF);
    float* sMG = (float*)(smem + MG_OFF);    // [w][t][18] = m, d, agg[16]
    float* sVC = (float*)(smem + VEC_OFF);
    float* sFN = (float*)(smem + FIN_OFF);
    float* sHD = (float*)(smem + HID_OFF);

    const int tid  = threadIdx.x;
    const int wid  = tid >> 5;
    const int lane = tid & 31;
    const int g    = lane >> 2;          // group (row within 8)
    const int t    = lane & 3;           // thread-in-group (k / col pair)
    const int bn   = blockIdx.x;
    const int b    = bn / NN;

    // ================= stage =================
    const float* rbf_bn = rbf + (size_t)bn * MM * NG;

    // rbf -> A region (cols 0..31), tf32-rounded; pad rows 99..127 with zero
    for (int idx = tid; idx < MM * (NG / 4); idx += 128) {
        int m  = idx >> 3;
        int c4 = idx & 7;
        float4 v = *(const float4*)(rbf_bn + m * NG + 4 * c4);
        v.x = to_tf32(v.x); v.y = to_tf32(v.y); v.z = to_tf32(v.z); v.w = to_tf32(v.w);
        *(float4*)(sU + m * U_STRIDE + 4 * c4) = v;
    }
    for (int idx = tid; idx < (128 - MM) * (NG / 4); idx += 128) {
        int m  = MM + (idx >> 3);
        int c4 = idx & 7;
        *(float4*)(sU + m * U_STRIDE + 4 * c4) = make_float4(0.f, 0.f, 0.f, 0.f);
    }
    // W1^T: sB1[n][k] = tf32(W1[k][n])
    for (int idx = tid; idx < NG * NF; idx += 128) {
        int k = idx >> 6, n = idx & 63;
        sB1[n * B1_STR + k] = to_tf32(W1[idx]);
    }
    // W2^T: sB2[n][k] = tf32(W2[k][n])
    for (int idx = tid; idx < NF * NF; idx += 128) {
        int k = idx >> 6, n = idx & 63;
        sB2[n * B2_STR + k] = to_tf32(W2[idx]);
    }
    // x rows for this frame: [100][66]
    {
        const float* gx = g_x + b * (NN * NF);
        for (int idx = tid; idx < NN * (NF / 4); idx += 128) {
            int r  = idx >> 4;
            int c4 = idx & 15;
            float4 v = *(const float4*)(gx + r * NF + 4 * c4);
            sX[r * X_STR + 4 * c4 + 0] = v.x;
            sX[r * X_STR + 4 * c4 + 1] = v.y;
            sX[r * X_STR + 4 * c4 + 2] = v.z;
            sX[r * X_STR + 4 * c4 + 3] = v.w;
        }
    }
    if (tid < NN) sNL[tid] = (tid < MM) ? nbr_list[bn * MM + tid] : 0;
    if (tid < NF) sBV[tid] = b1[tid];
    __syncthreads();

    // ================= GEMM1: D1[128,64] = A[128,32] @ W1 =================
    float acc[2][8][4];
#pragma unroll
    for (int mt = 0; mt < 2; mt++)
#pragma unroll
        for (int nt = 0; nt < 8; nt++)
#pragma unroll
            for (int c = 0; c < 4; c++) acc[mt][nt][c] = 0.f;

    const int wt0 = wid * 2;
#pragma unroll
    for (int ks = 0; ks < 4; ks++) {
        uint32_t a[2][4];
#pragma unroll
        for (int mt = 0; mt < 2; mt++) {
            int r = (wt0 + mt) * 16 + g;
            int k = ks * 8 + t;
            a[mt][0] = __float_as_uint(sU[r * U_STRIDE + k]);
            a[mt][1] = __float_as_uint(sU[(r + 8) * U_STRIDE + k]);
            a[mt][2] = __float_as_uint(sU[r * U_STRIDE + k + 4]);
            a[mt][3] = __float_as_uint(sU[(r + 8) * U_STRIDE + k + 4]);
        }
#pragma unroll
        for (int nt = 0; nt < 8; nt++) {
            int n = nt * 8 + g;
            int k = ks * 8 + t;
            uint32_t b0  = __float_as_uint(sB1[n * B1_STR + k]);
            uint32_t b1v = __float_as_uint(sB1[n * B1_STR + k + 4]);
            MMA_TF32(acc[0][nt], a[0], b0, b1v);
            MMA_TF32(acc[1][nt], a[1], b0, b1v);
        }
    }

    // ---- tanh(+b1) -> H in place (rows are warp-local; safe) ----
#pragma unroll
    for (int mt = 0; mt < 2; mt++) {
        int r0 = (wt0 + mt) * 16 + g;
        int r1 = r0 + 8;
#pragma unroll
        for (int nt = 0; nt < 8; nt++) {
            int c = 8 * nt + 2 * t;
            float2 v0, v1;
            v0.x = to_tf32(tanh_fast(acc[mt][nt][0] + sBV[c]));
            v0.y = to_tf32(tanh_fast(acc[mt][nt][1] + sBV[c + 1]));
            v1.x = to_tf32(tanh_fast(acc[mt][nt][2] + sBV[c]));
            v1.y = to_tf32(tanh_fast(acc[mt][nt][3] + sBV[c + 1]));
            *(float2*)(sU + r0 * U_STRIDE + c) = v0;
            *(float2*)(sU + r1 * U_STRIDE + c) = v1;
        }
    }
    __syncwarp();

    // ================= GEMM2: D2[128,64] = H[128,64] @ W2 =================
#pragma unroll
    for (int mt = 0; mt < 2; mt++)
#pragma unroll
        for (int nt = 0; nt < 8; nt++)
#pragma unroll
            for (int c = 0; c < 4; c++) acc[mt][nt][c] = 0.f;

#pragma unroll
    for (int ks = 0; ks < 8; ks++) {
        uint32_t a[2][4];
#pragma unroll
        for (int mt = 0; mt < 2; mt++) {
            int r = (wt0 + mt) * 16 + g;
            int k = ks * 8 + t;
            a[mt][0] = __float_as_uint(sU[r * U_STRIDE + k]);
            a[mt][1] = __float_as_uint(sU[(r + 8) * U_STRIDE + k]);
            a[mt][2] = __float_as_uint(sU[r * U_STRIDE + k + 4]);
            a[mt][3] = __float_as_uint(sU[(r + 8) * U_STRIDE + k + 4]);
        }
#pragma unroll
        for (int nt = 0; nt < 8; nt++) {
            int n = nt * 8 + g;
            int k = ks * 8 + t;
            uint32_t b0  = __float_as_uint(sB2[n * B2_STR + k]);
            uint32_t b1v = __float_as_uint(sB2[n * B2_STR + k + 4]);
            MMA_TF32(acc[0][nt], a[0], b0, b1v);
            MMA_TF32(acc[1][nt], a[1], b0, b1v);
        }
    }

    // ================= epilogue =================
    // this thread's 16 columns: c = 8*nt + 2*t + u
    float b2c[16], nfc[16];
#pragma unroll
    for (int nt = 0; nt < 8; nt++) {
        int c = 8 * nt + 2 * t;
        b2c[2 * nt]     = __ldg(b2 + c);
        b2c[2 * nt + 1] = __ldg(b2 + c + 1);
        nfc[2 * nt]     = __ldg(nbrf + c);
        nfc[2 * nt + 1] = __ldg(nbrf + c + 1);
    }

    float m_run = -1e30f, d_run = 0.f;
    float agg[16];
#pragma unroll
    for (int i = 0; i < 16; i++) agg[i] = 0.f;

#pragma unroll
    for (int mt = 0; mt < 2; mt++) {
        int r0 = (wt0 + mt) * 16 + g;
        int r1 = r0 + 8;
        bool v0 = r0 < MM, v1 = r1 < MM;
        int nb0 = v0 ? sNL[r0] : 0;
        int nb1 = v1 ? sNL[r1] : 0;
        float p0 = 0.f, p1 = 0.f;
#pragma unroll
        for (int nt = 0; nt < 8; nt++) {
            int c = 8 * nt + 2 * t;
            float2 x0 = *(const float2*)(sX + nb0 * X_STR + c);
            float2 x1 = *(const float2*)(sX + nb1 * X_STR + c);
            float cf00 = x0.x * (acc[mt][nt][0] + b2c[2 * nt]);
            float cf01 = x0.y * (acc[mt][nt][1] + b2c[2 * nt + 1]);
            float cf10 = x1.x * (acc[mt][nt][2] + b2c[2 * nt]);
            float cf11 = x1.y * (acc[mt][nt][3] + b2c[2 * nt + 1]);
            acc[mt][nt][0] = cf00; acc[mt][nt][1] = cf01;
            acc[mt][nt][2] = cf10; acc[mt][nt][3] = cf11;
            p0 += cf00 * nfc[2 * nt] + cf01 * nfc[2 * nt + 1];
            p1 += cf10 * nfc[2 * nt] + cf11 * nfc[2 * nt + 1];
        }
        // quad butterfly -> every lane holds row logit
        p0 += __shfl_xor_sync(0xffffffffu, p0, 1);
        p0 += __shfl_xor_sync(0xffffffffu, p0, 2);
        p1 += __shfl_xor_sync(0xffffffffu, p1, 1);
        p1 += __shfl_xor_sync(0xffffffffu, p1, 2);
        if (v0 && t == 0) sLG[r0] = p0;
        if (v1 && t == 0) sLG[r1] = p1;

        if (v0) {
            float mn = fmaxf(m_run, p0);
            float s  = __expf(m_run - mn);
            float e  = __expf(p0 - mn);
            d_run = d_run * s + e;
#pragma unroll
            for (int nt = 0; nt < 8; nt++) {
                agg[2 * nt]     = agg[2 * nt]     * s + e * acc[mt][nt][0];
                agg[2 * nt + 1] = agg[2 * nt + 1] * s + e * acc[mt][nt][1];
            }
            m_run = mn;
        }
        if (v1) {
            float mn = fmaxf(m_run, p1);
            float s  = __expf(m_run - mn);
            float e  = __expf(p1 - mn);
            d_run = d_run * s + e;
#pragma unroll
            for (int nt = 0; nt < 8; nt++) {
                agg[2 * nt]     = agg[2 * nt]     * s + e * acc[mt][nt][2];
                agg[2 * nt + 1] = agg[2 * nt + 1] * s + e * acc[mt][nt][3];
            }
            m_run = mn;
        }
    }

    // in-warp butterfly merge across row groups (offsets 4, 8, 16)
#pragma unroll
    for (int off = 4; off <= 16; off <<= 1) {
        float m2 = __shfl_xor_sync(0xffffffffu, m_run, off);
        float d2 = __shfl_xor_sync(0xffffffffu, d_run, off);
        float mn = fmaxf(m_run, m2);
        float s1 = __expf(m_run - mn);
        float s2 = __expf(m2 - mn);
        d_run = d_run * s1 + d2 * s2;
#pragma unroll
        for (int i = 0; i < 16; i++) {
            float a2 = __shfl_xor_sync(0xffffffffu, agg[i], off);
            agg[i] = agg[i] * s1 + a2 * s2;
        }
        m_run = mn;
    }

    // cross-warp merge via smem: lane<4 writes (m, d, agg[16])
    if (lane < 4) {
        float* dst = sMG + (wid * 4 + lane) * 18;
        dst[0] = m_run; dst[1] = d_run;
#pragma unroll
        for (int i = 0; i < 16; i++) dst[2 + i] = agg[i];
    }
    __syncthreads();

    if (tid < 4) {
        const float* s0 = sMG + (0 * 4 + tid) * 18;
        float mf = s0[0], df = s0[1], ag[16];
#pragma unroll
        for (int i = 0; i < 16; i++) ag[i] = s0[2 + i];
#pragma unroll
        for (int w = 1; w < 4; w++) {
            const float* sw = sMG + (w * 4 + tid) * 18;
            float m2 = sw[0], d2 = sw[1];
            float mn = fmaxf(mf, m2);
            float s1 = __expf(mf - mn);
            float s2 = __expf(m2 - mn);
            df = df * s1 + d2 * s2;
#pragma unroll
            for (int i = 0; i < 16; i++) ag[i] = ag[i] * s1 + sw[2 + i] * s2;
            mf = mn;
        }
        float inv = 1.f / df;
#pragma unroll
        for (int nt = 0; nt < 8; nt++) {
            int c = 8 * nt + 2 * tid;
            sVC[c]     = ag[2 * nt] * inv;
            sVC[c + 1] = ag[2 * nt + 1] * inv;
        }
        if (tid == 0) { sFN[0] = mf; sFN[1] = df; }
    }
    __syncthreads();

    // attn outputs
    if (tid < MM)
        attn[bn * MM + tid] = __expf(sLG[tid] - sFN[0]) / sFN[1];

    // output MLP
    const int j = tid & 63;
    const int h = tid >> 6;
    float tt = __ldg(b3 + j);
#pragma unroll
    for (int k = 0; k < NF; k++)
        tt = fmaf(sVC[k], __ldg(W3 + k * NF + j), tt);
    tt = tanh_fast(tt);
    if (h == 0) sHD[j] = tt;
    __syncthreads();
    if (h == 0) {
        float o = __ldg(b4 + j);
#pragma unroll
        for (int k = 0; k < NF; k++)
            o = fmaf(sHD[k], __ldg(W4 + k * NF + j), o);
        out[bn * NF + j] = o;
    }
}

// ---------------------------------------------------------------------------
extern "C" void kernel_launch(void* const* d_in, const int* in_sizes, int n_in,
                              void* d_out, int out_size)
{
    const float* features = (const float*)d_in[0];
    const float* rbf      = (const float*)d_in[1];
    const int*   nbr      = (const int*)  d_in[2];
    const float* W0       = (const float*)d_in[3];
    const float* W1       = (const float*)d_in[4];
    const float* b1       = (const float*)d_in[5];
    const float* W2       = (const float*)d_in[6];
    const float* b2       = (const float*)d_in[7];
    const float* nbrf     = (const float*)d_in[8];
    const float* W3       = (const float*)d_in[9];
    const float* b3       = (const float*)d_in[10];
    const float* W4       = (const float*)d_in[11];
    const float* b4       = (const float*)d_in[12];

    float* out  = (float*)d_out;                 // [B, N, NF]
    float* attn = out + BB * NN * NF;            // [B, N, M]

    cudaFuncSetAttribute(interaction_kernel,
                         cudaFuncAttributeMaxDynamicSharedMemorySize, SMEM_TOTAL);

    x_kernel<<<(BB * NN * NF + 255) / 256, 256>>>(features, W0);
    interaction_kernel<<<BB * NN, 128, SMEM_TOTAL>>>(rbf, nbr, W1, b1, W2, b2, nbrf,
                                                     W3, b3, W4, b4, out, attn);
}

// round 6
// speedup vs baseline: 3.8940x; 2.0414x over previous
#include <cuda_runtime.h>
#include <math.h>
#include <cstdint>

#define BB  64
#define NN  100
#define MM  99
#define NIN 32
#define NG  32
#define NF  64

// ---------------- smem layout (bytes), 2 atoms per CTA ---------------------
#define U_STRIDE 68
#define UBYTES   34816                   // [128][68] f32 per atom
#define B1_OFF   69632                   // W1^T [64][36]
#define B1_STR   36
#define B2_OFF   78848                   // W2^T [64][68]
#define B2_STR   68
#define SNL_OFF  96256                   // [2][100] int
#define SBV_OFF  97056                   // b1 [64]
#define SB2V_OFF 97312                   // b2 [64]
#define SNF_OFF  97568                   // nbrf [64]
#define SLG_OFF  97824                   // [2][100]
#define SMG_OFF  98624                   // [2][4][4][18]
#define SVC_OFF  100928                  // [2][64]
#define SFN_OFF  101440                  // [2][2]
#define SHD_OFF  101456                  // [2][64]
#define SMEM_TOTAL 102016

static __device__ __forceinline__ float tanh_fast(float x) {
    float y; asm("tanh.approx.f32 %0, %1;" : "=f"(y) : "f"(x)); return y;
}
static __device__ __forceinline__ float to_tf32(float x) {
    uint32_t u; asm("cvt.rna.tf32.f32 %0, %1;" : "=r"(u) : "f"(x));
    return __uint_as_float(u);
}

#define MMA_TF32(c, a, b0, b1v)                                                    \
    asm volatile("mma.sync.aligned.m16n8k8.row.col.f32.tf32.tf32.f32 "             \
        "{%0,%1,%2,%3},{%4,%5,%6,%7},{%8,%9},{%0,%1,%2,%3};"                       \
        : "+f"((c)[0]), "+f"((c)[1]), "+f"((c)[2]), "+f"((c)[3])                   \
        : "r"((a)[0]), "r"((a)[1]), "r"((a)[2]), "r"((a)[3]), "r"(b0), "r"(b1v))

__device__ float g_x[BB * NN * NF];       // x = features @ W0
__device__ float g_w1t[NF * NG];          // W1^T tf32  [n][k]
__device__ float g_w2t[NF * NF];          // W2^T tf32  [n][k]

// ---------------------------------------------------------------------------
__global__ void prep_kernel(const float* __restrict__ W1,
                            const float* __restrict__ W2)
{
    int idx = blockIdx.x * blockDim.x + threadIdx.x;
    if (idx < NF * NG) {                        // 2048
        int n = idx >> 5, k = idx & 31;
        g_w1t[n * NG + k] = to_tf32(W1[k * NF + n]);
    }
    int i2 = idx - NF * NG;
    if (i2 >= 0 && i2 < NF * NF) {              // 4096
        int n = i2 >> 6, k = i2 & 63;
        g_w2t[n * NF + k] = to_tf32(W2[k * NF + n]);
    }
}

__global__ void x_kernel(const float* __restrict__ features,
                         const float* __restrict__ W0)
{
    int idx = blockIdx.x * blockDim.x + threadIdx.x;
    if (idx >= BB * NN * NF) return;
    int f   = idx & (NF - 1);
    int row = idx >> 6;
    const float* feat = features + row * NIN;
    float acc = 0.f;
#pragma unroll
    for (int k = 0; k < NIN; k++)
        acc = fmaf(feat[k], W0[k * NF + f], acc);
    g_x[idx] = acc;
}

// ---------------------------------------------------------------------------
// One CTA per 2 atoms (same frame). 256 threads: warps 0-3 atom0, 4-7 atom1.
// ---------------------------------------------------------------------------
__global__ __launch_bounds__(256, 2)
void interaction_kernel(const float* __restrict__ rbf,
                        const int*   __restrict__ nbr_list,
                        const float* __restrict__ b1,
                        const float* __restrict__ b2,
                        const float* __restrict__ nbrf,
                        const float* __restrict__ W3, const float* __restrict__ b3,
                        const float* __restrict__ W4, const float* __restrict__ b4,
                        float* __restrict__ out,
                        float* __restrict__ attn)
{
    extern __shared__ __align__(16) char smem[];
    float* sB1 = (float*)(smem + B1_OFF);
    float* sB2 = (float*)(smem + B2_OFF);
    int*   sNL = (int*)  (smem + SNL_OFF);
    float* sBV = (float*)(smem + SBV_OFF);
    float* sB2V= (float*)(smem + SB2V_OFF);
    float* sNF = (float*)(smem + SNF_OFF);
    float* sLG = (float*)(smem + SLG_OFF);
    float* sMG = (float*)(smem + SMG_OFF);
    float* sVC = (float*)(smem + SVC_OFF);
    float* sFN = (float*)(smem + SFN_OFF);
    float* sHD = (float*)(smem + SHD_OFF);

    const int tid  = threadIdx.x;
    const int wid  = tid >> 5;
    const int lane = tid & 31;
    const int g    = lane >> 2;
    const int t    = lane & 3;
    const int a    = wid >> 2;            // atom within CTA (compute role)
    const int wt   = wid & 3;             // warp within atom group
    const int bn0  = blockIdx.x * 2;
    const int b    = bn0 / NN;

    // ================= stage =================
    // rbf for both atoms (tf32), rows 99..127 zero-padded
    for (int idx = tid; idx < 2 * 128 * 8; idx += 256) {
        int aa = idx >> 10;
        int r  = (idx >> 3) & 127;
        int c4 = idx & 7;
        float4 v = make_float4(0.f, 0.f, 0.f, 0.f);
        if (r < MM) {
            v = *(const float4*)(rbf + ((size_t)(bn0 + aa) * MM + r) * NG + 4 * c4);
            v.x = to_tf32(v.x); v.y = to_tf32(v.y);
            v.z = to_tf32(v.z); v.w = to_tf32(v.w);
        }
        *(float4*)(smem + aa * UBYTES + (r * U_STRIDE + 4 * c4) * 4) = v;
    }
    // B operands: vectorized copy from pre-transposed tf32 globals
    for (int idx = tid; idx < NF * 8; idx += 256) {          // B1: 512 float4
        int n = idx >> 3, c4 = idx & 7;
        *(float4*)(sB1 + n * B1_STR + 4 * c4) = *(const float4*)(g_w1t + n * NG + 4 * c4);
    }
    for (int idx = tid; idx < NF * 16; idx += 256) {         // B2: 1024 float4
        int n = idx >> 4, c4 = idx & 15;
        *(float4*)(sB2 + n * B2_STR + 4 * c4) = *(const float4*)(g_w2t + n * NF + 4 * c4);
    }
    if (tid < 200) {
        int aa = tid / 100, m = tid % 100;
        sNL[tid] = (m < MM) ? nbr_list[(bn0 + aa) * MM + m] : 0;
    }
    if (tid < NF) {
        sBV[tid]  = b1[tid];
        sB2V[tid] = b2[tid];
        sNF[tid]  = nbrf[tid];
    }
    __syncthreads();

    float* sU = (float*)(smem + a * UBYTES);
    const int wt0 = wt * 2;

    // ================= GEMM1: D1[128,64] = A[128,32] @ W1 =================
    float acc[2][8][4];
#pragma unroll
    for (int mt = 0; mt < 2; mt++)
#pragma unroll
        for (int nt = 0; nt < 8; nt++)
#pragma unroll
            for (int c = 0; c < 4; c++) acc[mt][nt][c] = 0.f;

#pragma unroll
    for (int ks = 0; ks < 4; ks++) {
        uint32_t af[2][4];
#pragma unroll
        for (int mt = 0; mt < 2; mt++) {
            int r = (wt0 + mt) * 16 + g;
            int k = ks * 8 + t;
            af[mt][0] = __float_as_uint(sU[r * U_STRIDE + k]);
            af[mt][1] = __float_as_uint(sU[(r + 8) * U_STRIDE + k]);
            af[mt][2] = __float_as_uint(sU[r * U_STRIDE + k + 4]);
            af[mt][3] = __float_as_uint(sU[(r + 8) * U_STRIDE + k + 4]);
        }
#pragma unroll
        for (int nt = 0; nt < 8; nt++) {
            int n = nt * 8 + g;
            int k = ks * 8 + t;
            uint32_t b0  = __float_as_uint(sB1[n * B1_STR + k]);
            uint32_t b1v = __float_as_uint(sB1[n * B1_STR + k + 4]);
            MMA_TF32(acc[0][nt], af[0], b0, b1v);
            MMA_TF32(acc[1][nt], af[1], b0, b1v);
        }
    }

    // ---- tanh(+b1) -> H in place (rows warp-local) ----
#pragma unroll
    for (int mt = 0; mt < 2; mt++) {
        int r0 = (wt0 + mt) * 16 + g;
        int r1 = r0 + 8;
#pragma unroll
        for (int nt = 0; nt < 8; nt++) {
            int c = 8 * nt + 2 * t;
            float2 v0, v1;
            v0.x = to_tf32(tanh_fast(acc[mt][nt][0] + sBV[c]));
            v0.y = to_tf32(tanh_fast(acc[mt][nt][1] + sBV[c + 1]));
            v1.x = to_tf32(tanh_fast(acc[mt][nt][2] + sBV[c]));
            v1.y = to_tf32(tanh_fast(acc[mt][nt][3] + sBV[c + 1]));
            *(float2*)(sU + r0 * U_STRIDE + c) = v0;
            *(float2*)(sU + r1 * U_STRIDE + c) = v1;
        }
    }
    __syncwarp();

    // ================= GEMM2: D2[128,64] = H[128,64] @ W2 =================
#pragma unroll
    for (int mt = 0; mt < 2; mt++)
#pragma unroll
        for (int nt = 0; nt < 8; nt++)
#pragma unroll
            for (int c = 0; c < 4; c++) acc[mt][nt][c] = 0.f;

#pragma unroll
    for (int ks = 0; ks < 8; ks++) {
        uint32_t af[2][4];
#pragma unroll
        for (int mt = 0; mt < 2; mt++) {
            int r = (wt0 + mt) * 16 + g;
            int k = ks * 8 + t;
            af[mt][0] = __float_as_uint(sU[r * U_STRIDE + k]);
            af[mt][1] = __float_as_uint(sU[(r + 8) * U_STRIDE + k]);
            af[mt][2] = __float_as_uint(sU[r * U_STRIDE + k + 4]);
            af[mt][3] = __float_as_uint(sU[(r + 8) * U_STRIDE + k + 4]);
        }
#pragma unroll
        for (int nt = 0; nt < 8; nt++) {
            int n = nt * 8 + g;
            int k = ks * 8 + t;
            uint32_t b0  = __float_as_uint(sB2[n * B2_STR + k]);
            uint32_t b1v = __float_as_uint(sB2[n * B2_STR + k + 4]);
            MMA_TF32(acc[0][nt], af[0], b0, b1v);
            MMA_TF32(acc[1][nt], af[1], b0, b1v);
        }
    }

    // ================= epilogue =================
    const float* gx_b = g_x + b * (NN * NF);
    const int*   nlA  = sNL + a * 100;
    float*       lgA  = sLG + a * 100;

    float m_run = -1e30f, d_run = 0.f;
    float agg[16];
#pragma unroll
    for (int i = 0; i < 16; i++) agg[i] = 0.f;

#pragma unroll
    for (int mt = 0; mt < 2; mt++) {
        int r0 = (wt0 + mt) * 16 + g;
        int r1 = r0 + 8;
        bool v0 = r0 < MM, v1 = r1 < MM;
        int nb0 = v0 ? nlA[r0] : 0;
        int nb1 = v1 ? nlA[r1] : 0;
        const float* x0p = gx_b + nb0 * NF;
        const float* x1p = gx_b + nb1 * NF;
        float p0 = 0.f, p1 = 0.f;
#pragma unroll
        for (int nt = 0; nt < 8; nt++) {
            int c = 8 * nt + 2 * t;
            float2 x0 = *(const float2*)(x0p + c);
            float2 x1 = *(const float2*)(x1p + c);
            float2 bb = *(const float2*)(sB2V + c);
            float2 nf = *(const float2*)(sNF + c);
            float cf00 = x0.x * (acc[mt][nt][0] + bb.x);
            float cf01 = x0.y * (acc[mt][nt][1] + bb.y);
            float cf10 = x1.x * (acc[mt][nt][2] + bb.x);
            float cf11 = x1.y * (acc[mt][nt][3] + bb.y);
            acc[mt][nt][0] = cf00; acc[mt][nt][1] = cf01;
            acc[mt][nt][2] = cf10; acc[mt][nt][3] = cf11;
            p0 += cf00 * nf.x + cf01 * nf.y;
            p1 += cf10 * nf.x + cf11 * nf.y;
        }
        p0 += __shfl_xor_sync(0xffffffffu, p0, 1);
        p0 += __shfl_xor_sync(0xffffffffu, p0, 2);
        p1 += __shfl_xor_sync(0xffffffffu, p1, 1);
        p1 += __shfl_xor_sync(0xffffffffu, p1, 2);
        if (v0 && t == 0) lgA[r0] = p0;
        if (v1 && t == 0) lgA[r1] = p1;

        if (v0) {
            float mn = fmaxf(m_run, p0);
            float s  = __expf(m_run - mn);
            float e  = __expf(p0 - mn);
            d_run = d_run * s + e;
#pragma unroll
            for (int nt = 0; nt < 8; nt++) {
                agg[2 * nt]     = agg[2 * nt]     * s + e * acc[mt][nt][0];
                agg[2 * nt + 1] = agg[2 * nt + 1] * s + e * acc[mt][nt][1];
            }
            m_run = mn;
        }
        if (v1) {
            float mn = fmaxf(m_run, p1);
            float s  = __expf(m_run - mn);
            float e  = __expf(p1 - mn);
            d_run = d_run * s + e;
#pragma unroll
            for (int nt = 0; nt < 8; nt++) {
                agg[2 * nt]     = agg[2 * nt]     * s + e * acc[mt][nt][2];
                agg[2 * nt + 1] = agg[2 * nt + 1] * s + e * acc[mt][nt][3];
            }
            m_run = mn;
        }
    }

    // in-warp butterfly merge across row groups
#pragma unroll
    for (int off = 4; off <= 16; off <<= 1) {
        float m2 = __shfl_xor_sync(0xffffffffu, m_run, off);
        float d2 = __shfl_xor_sync(0xffffffffu, d_run, off);
        float mn = fmaxf(m_run, m2);
        float s1 = __expf(m_run - mn);
        float s2 = __expf(m2 - mn);
        d_run = d_run * s1 + d2 * s2;
#pragma unroll
        for (int i = 0; i < 16; i++) {
            float a2 = __shfl_xor_sync(0xffffffffu, agg[i], off);
            agg[i] = agg[i] * s1 + a2 * s2;
        }
        m_run = mn;
    }

    // cross-warp merge via smem: lane<4 writes (m, d, agg[16]) per atom group
    if (lane < 4) {
        float* dst = sMG + (((a * 4 + wt) * 4) + lane) * 18;
        dst[0] = m_run; dst[1] = d_run;
#pragma unroll
        for (int i = 0; i < 16; i++) dst[2 + i] = agg[i];
    }
    __syncthreads();

    if (tid < 8) {
        int aa = tid >> 2, tt4 = tid & 3;
        const float* s0 = sMG + ((aa * 4 + 0) * 4 + tt4) * 18;
        float mf = s0[0], df = s0[1], ag[16];
#pragma unroll
        for (int i = 0; i < 16; i++) ag[i] = s0[2 + i];
#pragma unroll
        for (int w = 1; w < 4; w++) {
            const float* sw = sMG + ((aa * 4 + w) * 4 + tt4) * 18;
            float m2 = sw[0], d2 = sw[1];
            float mn = fmaxf(mf, m2);
            float s1 = __expf(mf - mn);
            float s2 = __expf(m2 - mn);
            df = df * s1 + d2 * s2;
#pragma unroll
            for (int i = 0; i < 16; i++) ag[i] = ag[i] * s1 + sw[2 + i] * s2;
            mf = mn;
        }
        float inv = 1.f / df;
#pragma unroll
        for (int nt = 0; nt < 8; nt++) {
            int c = 8 * nt + 2 * tt4;
            sVC[aa * 64 + c]     = ag[2 * nt] * inv;
            sVC[aa * 64 + c + 1] = ag[2 * nt + 1] * inv;
        }
        if (tt4 == 0) { sFN[2 * aa] = mf; sFN[2 * aa + 1] = df; }
    }
    __syncthreads();

    // attn outputs (threads 0..127 -> atom0, 128..255 -> atom1)
    {
        int aa  = tid >> 7;
        int ltd = tid & 127;
        if (ltd < MM)
            attn[(bn0 + aa) * MM + ltd] =
                __expf(sLG[aa * 100 + ltd] - sFN[2 * aa]) / sFN[2 * aa + 1];
    }

    // output MLP (per atom: 128 threads, redundant halves)
    {
        int aa  = tid >> 7;
        int ltd = tid & 127;
        int j   = ltd & 63;
        int hh  = ltd >> 6;
        const float* vc = sVC + aa * 64;
        float tt = __ldg(b3 + j);
#pragma unroll
        for (int k = 0; k < NF; k++)
            tt = fmaf(vc[k], __ldg(W3 + k * NF + j), tt);
        tt = tanh_fast(tt);
        if (hh == 0) sHD[aa * 64 + j] = tt;
        __syncthreads();
        if (hh == 0) {
            const float* hd = sHD + aa * 64;
            float o = __ldg(b4 + j);
#pragma unroll
            for (int k = 0; k < NF; k++)
                o = fmaf(hd[k], __ldg(W4 + k * NF + j), o);
            out[(bn0 + aa) * NF + j] = o;
        }
    }
}

// ---------------------------------------------------------------------------
extern "C" void kernel_launch(void* const* d_in, const int* in_sizes, int n_in,
                              void* d_out, int out_size)
{
    const float* features = (const float*)d_in[0];
    const float* rbf      = (const float*)d_in[1];
    const int*   nbr      = (const int*)  d_in[2];
    const float* W0       = (const float*)d_in[3];
    const float* W1       = (const float*)d_in[4];
    const float* b1       = (const float*)d_in[5];
    const float* W2       = (const float*)d_in[6];
    const float* b2       = (const float*)d_in[7];
    const float* nbrf     = (const float*)d_in[8];
    const float* W3       = (const float*)d_in[9];
    const float* b3       = (const float*)d_in[10];
    const float* W4       = (const float*)d_in[11];
    const float* b4       = (const float*)d_in[12];

    float* out  = (float*)d_out;                 // [B, N, NF]
    float* attn = out + BB * NN * NF;            // [B, N, M]

    cudaFuncSetAttribute(interaction_kernel,
                         cudaFuncAttributeMaxDynamicSharedMemorySize, SMEM_TOTAL);

    prep_kernel<<<24, 256>>>(W1, W2);
    x_kernel<<<(BB * NN * NF + 255) / 256, 256>>>(features, W0);
    interaction_kernel<<<BB * NN / 2, 256, SMEM_TOTAL>>>(rbf, nbr, b1, b2, nbrf,
                                                         W3, b3, W4, b4, out, attn);
}

// round 7
// speedup vs baseline: 4.2785x; 1.0987x over previous
#include <cuda_runtime.h>
#include <math.h>
#include <cstdint>

#define BB  64
#define NN  100
#define MM  99
#define NIN 32
#define NG  32
#define NF  64

// ---------------- smem layout (bytes) --------------------------------------
// Per-warp U slab: [16][68] f32 = 4352 B, 8 warps = 34816 B
#define U_STRIDE 68
#define UW_BYTES 4352
#define B1_OFF   34816                   // W1^T [64][36]
#define B1_STR   36
#define B2_OFF   44032                   // W2^T [64][68]
#define B2_STR   68
#define SNL_OFF  61440                   // [2][100] int
#define SBV_OFF  62240                   // b1 [64]
#define SB2V_OFF 62496                   // b2 [64]
#define SNF_OFF  62752                   // nbrf [64]
#define SLG_OFF  63008                   // [2][100]
#define SMG_OFF  63808                   // [2][4][4][18] f32
#define SVC_OFF  66112                   // [2][64]
#define SFN_OFF  66624                   // [2][2]
#define SHD_OFF  66640                   // [2][64]
#define SMEM_TOTAL 67200

static __device__ __forceinline__ float tanh_fast(float x) {
    float y; asm("tanh.approx.f32 %0, %1;" : "=f"(y) : "f"(x)); return y;
}
static __device__ __forceinline__ float to_tf32(float x) {
    uint32_t u; asm("cvt.rna.tf32.f32 %0, %1;" : "=r"(u) : "f"(x));
    return __uint_as_float(u);
}

#define MMA_TF32(c, a, b0, b1v)                                                    \
    asm volatile("mma.sync.aligned.m16n8k8.row.col.f32.tf32.tf32.f32 "             \
        "{%0,%1,%2,%3},{%4,%5,%6,%7},{%8,%9},{%0,%1,%2,%3};"                       \
        : "+f"((c)[0]), "+f"((c)[1]), "+f"((c)[2]), "+f"((c)[3])                   \
        : "r"((a)[0]), "r"((a)[1]), "r"((a)[2]), "r"((a)[3]), "r"(b0), "r"(b1v))

__device__ float g_x[BB * NN * NF];       // x = features @ W0
__device__ float g_w1t[NF * NG];          // W1^T tf32  [n][k]
__device__ float g_w2t[NF * NF];          // W2^T tf32  [n][k]

// ---------------------------------------------------------------------------
// Fused setup: weight transposes + x = features @ W0
// ---------------------------------------------------------------------------
#define SETUP_W (NF * NG + NF * NF)       // 6144
__global__ void setup_kernel(const float* __restrict__ W1,
                             const float* __restrict__ W2,
                             const float* __restrict__ features,
                             const float* __restrict__ W0)
{
    int idx = blockIdx.x * blockDim.x + threadIdx.x;
    if (idx < NF * NG) {
        int n = idx >> 5, k = idx & 31;
        g_w1t[n * NG + k] = to_tf32(W1[k * NF + n]);
        return;
    }
    if (idx < SETUP_W) {
        int i2 = idx - NF * NG;
        int n = i2 >> 6, k = i2 & 63;
        g_w2t[n * NF + k] = to_tf32(W2[k * NF + n]);
        return;
    }
    int ix = idx - SETUP_W;
    if (ix >= BB * NN * NF) return;
    int f   = ix & (NF - 1);
    int row = ix >> 6;
    const float* feat = features + row * NIN;
    float acc = 0.f;
#pragma unroll
    for (int k = 0; k < NIN; k++)
        acc = fmaf(feat[k], W0[k * NF + f], acc);
    g_x[ix] = acc;
}

// ---------------------------------------------------------------------------
// One CTA per 2 atoms. 256 threads: warps 0-3 atom0, 4-7 atom1.
// Each warp owns rows [32*wt, 32*wt+32) of its atom, processed as two
// 16-row chunks through a private smem slab: stage -> GEMM1 -> tanh ->
// GEMM2 -> epilogue, all warp-local (no block barriers until merge).
// ---------------------------------------------------------------------------
__global__ __launch_bounds__(256, 3)
void interaction_kernel(const float* __restrict__ rbf,
                        const int*   __restrict__ nbr_list,
                        const float* __restrict__ b1,
                        const float* __restrict__ b2,
                        const float* __restrict__ nbrf,
                        const float* __restrict__ W3, const float* __restrict__ b3,
                        const float* __restrict__ W4, const float* __restrict__ b4,
                        float* __restrict__ out,
                        float* __restrict__ attn)
{
    extern __shared__ __align__(16) char smem[];
    float* sB1 = (float*)(smem + B1_OFF);
    float* sB2 = (float*)(smem + B2_OFF);
    int*   sNL = (int*)  (smem + SNL_OFF);
    float* sBV = (float*)(smem + SBV_OFF);
    float* sB2V= (float*)(smem + SB2V_OFF);
    float* sNF = (float*)(smem + SNF_OFF);
    float* sLG = (float*)(smem + SLG_OFF);
    float* sMG = (float*)(smem + SMG_OFF);
    float* sVC = (float*)(smem + SVC_OFF);
    float* sFN = (float*)(smem + SFN_OFF);
    float* sHD = (float*)(smem + SHD_OFF);

    const int tid  = threadIdx.x;
    const int wid  = tid >> 5;
    const int lane = tid & 31;
    const int g    = lane >> 2;
    const int t    = lane & 3;
    const int a    = wid >> 2;            // atom within CTA
    const int wt   = wid & 3;             // warp within atom group
    const int bn0  = blockIdx.x * 2;
    const int b    = bn0 / NN;

    // ---- cooperative stage of shared operands (one barrier) ----
    for (int idx = tid; idx < NF * 8; idx += 256) {          // B1
        int n = idx >> 3, c4 = idx & 7;
        *(float4*)(sB1 + n * B1_STR + 4 * c4) = *(const float4*)(g_w1t + n * NG + 4 * c4);
    }
    for (int idx = tid; idx < NF * 16; idx += 256) {         // B2
        int n = idx >> 4, c4 = idx & 15;
        *(float4*)(sB2 + n * B2_STR + 4 * c4) = *(const float4*)(g_w2t + n * NF + 4 * c4);
    }
    if (tid < 200) {
        int aa = tid / 100, m = tid % 100;
        sNL[tid] = (m < MM) ? nbr_list[(bn0 + aa) * MM + m] : 0;
    }
    if (tid < NF) {
        sBV[tid]  = b1[tid];
        sB2V[tid] = b2[tid];
        sNF[tid]  = nbrf[tid];
    }
    __syncthreads();

    float* sU = (float*)(smem + wid * UW_BYTES);     // warp-private [16][68]
    const float* rbf_a = rbf + (size_t)(bn0 + a) * MM * NG;
    const float* gx_b  = g_x + b * (NN * NF);
    const int*   nlA   = sNL + a * 100;
    float*       lgA   = sLG + a * 100;

    float m_run = -1e30f, d_run = 0.f;
    float agg[16];
#pragma unroll
    for (int i = 0; i < 16; i++) agg[i] = 0.f;

#pragma unroll
    for (int mt = 0; mt < 2; mt++) {
        const int rowbase = (wt * 2 + mt) * 16;

        // ---- warp-local stage: 16 rows x 32 cols (tf32) ----
#pragma unroll
        for (int q = 0; q < 4; q++) {
            int idx = q * 32 + lane;      // 0..127
            int r   = idx >> 3;
            int c4  = idx & 7;
            int grow = rowbase + r;
            float4 v = make_float4(0.f, 0.f, 0.f, 0.f);
            if (grow < MM) {
                v = *(const float4*)(rbf_a + (size_t)grow * NG + 4 * c4);
                v.x = to_tf32(v.x); v.y = to_tf32(v.y);
                v.z = to_tf32(v.z); v.w = to_tf32(v.w);
            }
            *(float4*)(sU + r * U_STRIDE + 4 * c4) = v;
        }
        __syncwarp();

        // ---- GEMM1: D1[16,64] = A[16,32] @ W1 ----
        float acc[8][4];
#pragma unroll
        for (int nt = 0; nt < 8; nt++)
#pragma unroll
            for (int c = 0; c < 4; c++) acc[nt][c] = 0.f;

#pragma unroll
        for (int ks = 0; ks < 4; ks++) {
            int k = ks * 8 + t;
            uint32_t af[4];
            af[0] = __float_as_uint(sU[g * U_STRIDE + k]);
            af[1] = __float_as_uint(sU[(g + 8) * U_STRIDE + k]);
            af[2] = __float_as_uint(sU[g * U_STRIDE + k + 4]);
            af[3] = __float_as_uint(sU[(g + 8) * U_STRIDE + k + 4]);
#pragma unroll
            for (int nt = 0; nt < 8; nt++) {
                int n = nt * 8 + g;
                uint32_t b0  = __float_as_uint(sB1[n * B1_STR + k]);
                uint32_t b1v = __float_as_uint(sB1[n * B1_STR + k + 4]);
                MMA_TF32(acc[nt], af, b0, b1v);
            }
        }
        __syncwarp();

        // ---- tanh(+b1) -> H in place ----
#pragma unroll
        for (int nt = 0; nt < 8; nt++) {
            int c = 8 * nt + 2 * t;
            float2 v0, v1;
            v0.x = to_tf32(tanh_fast(acc[nt][0] + sBV[c]));
            v0.y = to_tf32(tanh_fast(acc[nt][1] + sBV[c + 1]));
            v1.x = to_tf32(tanh_fast(acc[nt][2] + sBV[c]));
            v1.y = to_tf32(tanh_fast(acc[nt][3] + sBV[c + 1]));
            *(float2*)(sU + g * U_STRIDE + c)       = v0;
            *(float2*)(sU + (g + 8) * U_STRIDE + c) = v1;
        }
        __syncwarp();

        // ---- GEMM2: D2[16,64] = H[16,64] @ W2 ----
#pragma unroll
        for (int nt = 0; nt < 8; nt++)
#pragma unroll
            for (int c = 0; c < 4; c++) acc[nt][c] = 0.f;

#pragma unroll
        for (int ks = 0; ks < 8; ks++) {
            int k = ks * 8 + t;
            uint32_t af[4];
            af[0] = __float_as_uint(sU[g * U_STRIDE + k]);
            af[1] = __float_as_uint(sU[(g + 8) * U_STRIDE + k]);
            af[2] = __float_as_uint(sU[g * U_STRIDE + k + 4]);
            af[3] = __float_as_uint(sU[(g + 8) * U_STRIDE + k + 4]);
#pragma unroll
            for (int nt = 0; nt < 8; nt++) {
                int n = nt * 8 + g;
                uint32_t b0  = __float_as_uint(sB2[n * B2_STR + k]);
                uint32_t b1v = __float_as_uint(sB2[n * B2_STR + k + 4]);
                MMA_TF32(acc[nt], af, b0, b1v);
            }
        }

        // ---- epilogue for this chunk's 2 rows per lane ----
        {
            int r0 = rowbase + g;
            int r1 = r0 + 8;
            bool v0 = r0 < MM, v1 = r1 < MM;
            int nb0 = v0 ? nlA[r0] : 0;
            int nb1 = v1 ? nlA[r1] : 0;
            const float* x0p = gx_b + nb0 * NF;
            const float* x1p = gx_b + nb1 * NF;
            float p0 = 0.f, p1 = 0.f;
#pragma unroll
            for (int nt = 0; nt < 8; nt++) {
                int c = 8 * nt + 2 * t;
                float2 x0 = *(const float2*)(x0p + c);
                float2 x1 = *(const float2*)(x1p + c);
                float2 bb = *(const float2*)(sB2V + c);
                float2 nf = *(const float2*)(sNF + c);
                float cf00 = x0.x * (acc[nt][0] + bb.x);
                float cf01 = x0.y * (acc[nt][1] + bb.y);
                float cf10 = x1.x * (acc[nt][2] + bb.x);
                float cf11 = x1.y * (acc[nt][3] + bb.y);
                acc[nt][0] = cf00; acc[nt][1] = cf01;
                acc[nt][2] = cf10; acc[nt][3] = cf11;
                p0 += cf00 * nf.x + cf01 * nf.y;
                p1 += cf10 * nf.x + cf11 * nf.y;
            }
            p0 += __shfl_xor_sync(0xffffffffu, p0, 1);
            p0 += __shfl_xor_sync(0xffffffffu, p0, 2);
            p1 += __shfl_xor_sync(0xffffffffu, p1, 1);
            p1 += __shfl_xor_sync(0xffffffffu, p1, 2);
            if (v0 && t == 0) lgA[r0] = p0;
            if (v1 && t == 0) lgA[r1] = p1;

            if (v0) {
                float mn = fmaxf(m_run, p0);
                float s  = __expf(m_run - mn);
                float e  = __expf(p0 - mn);
                d_run = d_run * s + e;
#pragma unroll
                for (int nt = 0; nt < 8; nt++) {
                    agg[2 * nt]     = agg[2 * nt]     * s + e * acc[nt][0];
                    agg[2 * nt + 1] = agg[2 * nt + 1] * s + e * acc[nt][1];
                }
                m_run = mn;
            }
            if (v1) {
                float mn = fmaxf(m_run, p1);
                float s  = __expf(m_run - mn);
                float e  = __expf(p1 - mn);
                d_run = d_run * s + e;
#pragma unroll
                for (int nt = 0; nt < 8; nt++) {
                    agg[2 * nt]     = agg[2 * nt]     * s + e * acc[nt][2];
                    agg[2 * nt + 1] = agg[2 * nt + 1] * s + e * acc[nt][3];
                }
                m_run = mn;
            }
        }
        __syncwarp();
    }

    // ---- in-warp butterfly merge across row groups ----
#pragma unroll
    for (int off = 4; off <= 16; off <<= 1) {
        float m2 = __shfl_xor_sync(0xffffffffu, m_run, off);
        float d2 = __shfl_xor_sync(0xffffffffu, d_run, off);
        float mn = fmaxf(m_run, m2);
        float s1 = __expf(m_run - mn);
        float s2 = __expf(m2 - mn);
        d_run = d_run * s1 + d2 * s2;
#pragma unroll
        for (int i = 0; i < 16; i++) {
            float a2 = __shfl_xor_sync(0xffffffffu, agg[i], off);
            agg[i] = agg[i] * s1 + a2 * s2;
        }
        m_run = mn;
    }

    // ---- cross-warp merge via smem ----
    if (lane < 4) {
        float* dst = sMG + (((a * 4 + wt) * 4) + lane) * 18;
        dst[0] = m_run; dst[1] = d_run;
#pragma unroll
        for (int i = 0; i < 16; i++) dst[2 + i] = agg[i];
    }
    __syncthreads();

    if (tid < 8) {
        int aa = tid >> 2, tt4 = tid & 3;
        const float* s0 = sMG + ((aa * 4 + 0) * 4 + tt4) * 18;
        float mf = s0[0], df = s0[1], ag[16];
#pragma unroll
        for (int i = 0; i < 16; i++) ag[i] = s0[2 + i];
#pragma unroll
        for (int w = 1; w < 4; w++) {
            const float* sw = sMG + ((aa * 4 + w) * 4 + tt4) * 18;
            float m2 = sw[0], d2 = sw[1];
            float mn = fmaxf(mf, m2);
            float s1 = __expf(mf - mn);
            float s2 = __expf(m2 - mn);
            df = df * s1 + d2 * s2;
#pragma unroll
            for (int i = 0; i < 16; i++) ag[i] = ag[i] * s1 + sw[2 + i] * s2;
            mf = mn;
        }
        float inv = 1.f / df;
#pragma unroll
        for (int nt = 0; nt < 8; nt++) {
            int c = 8 * nt + 2 * tt4;
            sVC[aa * 64 + c]     = ag[2 * nt] * inv;
            sVC[aa * 64 + c + 1] = ag[2 * nt + 1] * inv;
        }
        if (tt4 == 0) { sFN[2 * aa] = mf; sFN[2 * aa + 1] = df; }
    }
    __syncthreads();

    // ---- attn outputs ----
    {
        int aa  = tid >> 7;
        int ltd = tid & 127;
        if (ltd < MM)
            attn[(bn0 + aa) * MM + ltd] =
                __expf(sLG[aa * 100 + ltd] - sFN[2 * aa]) / sFN[2 * aa + 1];
    }

    // ---- output MLP ----
    {
        int aa  = tid >> 7;
        int ltd = tid & 127;
        int j   = ltd & 63;
        int hh  = ltd >> 6;
        const float* vc = sVC + aa * 64;
        float tt = __ldg(b3 + j);
#pragma unroll
        for (int k = 0; k < NF; k++)
            tt = fmaf(vc[k], __ldg(W3 + k * NF + j), tt);
        tt = tanh_fast(tt);
        if (hh == 0) sHD[aa * 64 + j] = tt;
        __syncthreads();
        if (hh == 0) {
            const float* hd = sHD + aa * 64;
            float o = __ldg(b4 + j);
#pragma unroll
            for (int k = 0; k < NF; k++)
                o = fmaf(hd[k], __ldg(W4 + k * NF + j), o);
            out[(bn0 + aa) * NF + j] = o;
        }
    }
}

// ---------------------------------------------------------------------------
extern "C" void kernel_launch(void* const* d_in, const int* in_sizes, int n_in,
                              void* d_out, int out_size)
{
    const float* features = (const float*)d_in[0];
    const float* rbf      = (const float*)d_in[1];
    const int*   nbr      = (const int*)  d_in[2];
    const float* W0       = (const float*)d_in[3];
    const float* W1       = (const float*)d_in[4];
    const float* b1       = (const float*)d_in[5];
    const float* W2       = (const float*)d_in[6];
    const float* b2       = (const float*)d_in[7];
    const float* nbrf     = (const float*)d_in[8];
    const float* W3       = (const float*)d_in[9];
    const float* b3       = (const float*)d_in[10];
    const float* W4       = (const float*)d_in[11];
    const float* b4       = (const float*)d_in[12];

    float* out  = (float*)d_out;                 // [B, N, NF]
    float* attn = out + BB * NN * NF;            // [B, N, M]

    cudaFuncSetAttribute(interaction_kernel,
                         cudaFuncAttributeMaxDynamicSharedMemorySize, SMEM_TOTAL);

    const int setup_elems = SETUP_W + BB * NN * NF;
    setup_kernel<<<(setup_elems + 255) / 256, 256>>>(W1, W2, features, W0);
    interaction_kernel<<<BB * NN / 2, 256, SMEM_TOTAL>>>(rbf, nbr, b1, b2, nbrf,
                                                         W3, b3, W4, b4, out, attn);
}